// round 16
// baseline (speedup 1.0000x reference)
#include <cuda_runtime.h>
#include <cuda_bf16.h>
#include <math.h>
#include <cstdint>

#define BATCH 4
#define SEQ   4096
#define EMB   1024
#define HEAD  64

// bf16 hi/lo split of projected q (pre-scaled by 0.125*log2e), k, v. 2 MB each.
__device__ __nv_bfloat16 g_qhi[BATCH * SEQ * HEAD];
__device__ __nv_bfloat16 g_qlo[BATCH * SEQ * HEAD];
__device__ __nv_bfloat16 g_khi[BATCH * SEQ * HEAD];
__device__ __nv_bfloat16 g_klo[BATCH * SEQ * HEAD];
__device__ __nv_bfloat16 g_vhi[BATCH * SEQ * HEAD];
__device__ __nv_bfloat16 g_vlo[BATCH * SEQ * HEAD];

// W^T hi/lo: [n=192][k=1024]
__device__ __nv_bfloat16 g_wthi[192 * 1024];
__device__ __nv_bfloat16 g_wtlo[192 * 1024];

// split-K partials (BQ=128 layout: pidx < 512, 128 rows x 64 cols)
__device__ float g_opart[512 * 128 * 64];   // 16 MB
__device__ float g_mpart[512 * 128];
__device__ float g_lpart[512 * 128];

#define QSCALE 0.18033688011112042f   // 0.125 * log2(e)

// ===========================================================================
// helpers
// ===========================================================================
__device__ __forceinline__ uint32_t smem_u32(const void* p) {
    uint32_t a;
    asm("{ .reg .u64 t; cvta.to.shared.u64 t, %1; cvt.u32.u64 %0, t; }"
        : "=r"(a) : "l"(p));
    return a;
}

__device__ __forceinline__ void ldsm4(uint32_t addr, uint32_t* r) {
    asm volatile("ldmatrix.sync.aligned.m8n8.x4.shared.b16 {%0,%1,%2,%3}, [%4];"
        : "=r"(r[0]), "=r"(r[1]), "=r"(r[2]), "=r"(r[3]) : "r"(addr));
}
__device__ __forceinline__ void ldsm4t(uint32_t addr, uint32_t* r) {
    asm volatile("ldmatrix.sync.aligned.m8n8.x4.trans.shared.b16 {%0,%1,%2,%3}, [%4];"
        : "=r"(r[0]), "=r"(r[1]), "=r"(r[2]), "=r"(r[3]) : "r"(addr));
}

__device__ __forceinline__ void mma16816(float* c, const uint32_t* a,
                                         uint32_t b0, uint32_t b1) {
    asm volatile(
        "mma.sync.aligned.m16n8k16.row.col.f32.bf16.bf16.f32 "
        "{%0,%1,%2,%3}, {%4,%5,%6,%7}, {%8,%9}, {%0,%1,%2,%3};"
        : "+f"(c[0]), "+f"(c[1]), "+f"(c[2]), "+f"(c[3])
        : "r"(a[0]), "r"(a[1]), "r"(a[2]), "r"(a[3]), "r"(b0), "r"(b1));
}

__device__ __forceinline__ void cp_async16(uint32_t saddr, const void* gaddr) {
    asm volatile("cp.async.cg.shared.global [%0], [%1], 16;"
        :: "r"(saddr), "l"(gaddr) : "memory");
}
#define CP_COMMIT() asm volatile("cp.async.commit_group;" ::: "memory")

#define STS128(r0, r1, r2, r3, addr) \
    asm volatile("st.shared.v4.b32 [%0], {%1, %2, %3, %4};" \
        :: "r"(addr), "r"(r0), "r"(r1), "r"(r2), "r"(r3) : "memory")

// fast fp32 pair -> bf16 hi word + bf16 residual word (rn, exact residual)
__device__ __forceinline__ void split2(float x0, float x1,
                                       uint32_t& hw, uint32_t& lw) {
    asm("cvt.rn.bf16x2.f32 %0, %1, %2;" : "=r"(hw) : "f"(x1), "f"(x0));
    const float h0 = __uint_as_float(hw << 16);
    const float h1 = __uint_as_float(hw & 0xFFFF0000u);
    const float l0 = x0 - h0;
    const float l1 = x1 - h1;
    asm("cvt.rn.bf16x2.f32 %0, %1, %2;" : "=r"(lw) : "f"(l1), "f"(l0));
}

// ===========================================================================
// Kernel 0: W^T hi/lo precompute — simple version (6.4us measured)
// ===========================================================================
__global__ __launch_bounds__(256) void wconv_kernel(
    const float* __restrict__ Wq, const float* __restrict__ Wk,
    const float* __restrict__ Wv)
{
    const int n = blockIdx.x;
    const float* W;
    int nn;
    if (n < 64)       { W = Wq; nn = n; }
    else if (n < 128) { W = Wk; nn = n - 64; }
    else              { W = Wv; nn = n - 128; }
    for (int k = threadIdx.x; k < 1024; k += 256) {
        float v = W[(size_t)k * HEAD + nn];
        __nv_bfloat16 h = __float2bfloat16(v);
        float l = v - __bfloat162float(h);
        g_wthi[(size_t)n * 1024 + k] = h;
        g_wtlo[(size_t)n * 1024 + k] = __float2bfloat16(l);
    }
}

// ===========================================================================
// Kernel 1: QKV projection on mma.sync (3xBF16). 512 threads, 16 warps.
// (R11/R14 version, unchanged.)
// ===========================================================================
#define QK_STG  92160
#define QX_HI   0
#define QX_LO   18432
#define QW_HI   36864
#define QW_LO   64512
#define QK_SMEM (2 * QK_STG)
#define NCH     (EMB / 64)

__global__ __launch_bounds__(512, 1) void qkv_mma_kernel(
    const float* __restrict__ x,
    const float* __restrict__ bq, const float* __restrict__ bk,
    const float* __restrict__ bv)
{
    extern __shared__ char smem[];
    const uint32_t sbase = smem_u32(smem);
    const int tid  = threadIdx.x;
    const int warp = tid >> 5;
    const int lane = tid & 31;
    const int g    = lane >> 2;
    const int qr   = lane & 3;
    const int warpM = warp >> 1;
    const int warpN = warp & 1;
    const int m0 = blockIdx.x * 128;

    const int xrow = tid >> 2;
    const int xq   = (tid & 3) * 16;

    float xr[16];

    auto ldX = [&](int c) {
        const float4* src = reinterpret_cast<const float4*>(
            x + (size_t)(m0 + xrow) * EMB + c * 64 + xq);
#pragma unroll
        for (int j = 0; j < 4; j++) {
            float4 v = src[j];
            xr[j * 4 + 0] = v.x; xr[j * 4 + 1] = v.y;
            xr[j * 4 + 2] = v.z; xr[j * 4 + 3] = v.w;
        }
    };

    auto stX = [&](int s) {
        const uint32_t dst = sbase + s * QK_STG
            + (uint32_t)xrow * 144 + xq * 2;
        uint32_t hw[8], lw[8];
#pragma unroll
        for (int p = 0; p < 8; p++)
            split2(xr[p * 2], xr[p * 2 + 1], hw[p], lw[p]);
        STS128(hw[0], hw[1], hw[2], hw[3], dst + QX_HI);
        STS128(hw[4], hw[5], hw[6], hw[7], dst + QX_HI + 16);
        STS128(lw[0], lw[1], lw[2], lw[3], dst + QX_LO);
        STS128(lw[4], lw[5], lw[6], lw[7], dst + QX_LO + 16);
    };

    auto cpW = [&](int c, int s) {
        const uint32_t base = sbase + s * QK_STG;
#pragma unroll
        for (int t = 0; t < 6; t++) {
            const int i   = tid + t * 512;
            const int arr = (i >= 1536) ? 1 : 0;
            const int i2  = arr ? (i - 1536) : i;
            const int row = i2 >> 3, ch = i2 & 7;
            const __nv_bfloat16* src = (arr ? g_wtlo : g_wthi)
                + (size_t)row * 1024 + c * 64 + ch * 8;
            cp_async16(base + (arr ? QW_LO : QW_HI) + row * 144 + ch * 16, src);
        }
        CP_COMMIT();
    };

    float acc[12][4];
#pragma unroll
    for (int nt = 0; nt < 12; nt++)
#pragma unroll
        for (int e = 0; e < 4; e++) acc[nt][e] = 0.0f;

    ldX(0);
    cpW(0, 0);

    for (int c = 0; c < NCH; c++) {
        const int s = c & 1;
        __syncthreads();
        stX(s);
        if (c + 1 < NCH) {
            cpW(c + 1, s ^ 1);
            asm volatile("cp.async.wait_group 1;" ::: "memory");
        } else {
            asm volatile("cp.async.wait_group 0;" ::: "memory");
        }
        __syncthreads();
        if (c + 1 < NCH) ldX(c + 1);

        const uint32_t xb = sbase + s * QK_STG + QX_HI
            + (uint32_t)(warpM * 16 + (lane & 15)) * 144 + (lane >> 4) * 16;
        const uint32_t wb = sbase + s * QK_STG + QW_HI
            + (uint32_t)(warpN * 96 + ((lane >> 4) & 1) * 8 + (lane & 7)) * 144
            + ((lane >> 3) & 1) * 16;

#pragma unroll
        for (int kc = 0; kc < 4; kc++) {
            uint32_t ah[4], al[4];
            ldsm4(xb + kc * 32, ah);
            ldsm4(xb + (QX_LO - QX_HI) + kc * 32, al);
#pragma unroll
            for (int nt = 0; nt < 6; nt++) {
                uint32_t bh[4], bl[4];
                ldsm4(wb + nt * (16 * 144) + kc * 32, bh);
                ldsm4(wb + (QW_LO - QW_HI) + nt * (16 * 144) + kc * 32, bl);
                mma16816(acc[2 * nt],     ah, bh[0], bh[1]);
                mma16816(acc[2 * nt],     ah, bl[0], bl[1]);
                mma16816(acc[2 * nt],     al, bh[0], bh[1]);
                mma16816(acc[2 * nt + 1], ah, bh[2], bh[3]);
                mma16816(acc[2 * nt + 1], ah, bl[2], bl[3]);
                mma16816(acc[2 * nt + 1], al, bh[2], bh[3]);
            }
        }
    }

    {
        const int rbase = m0 + warpM * 16 + g;
#pragma unroll
        for (int nt = 0; nt < 12; nt++) {
            const int cc = warpN * 96 + nt * 8 + qr * 2;
#pragma unroll
            for (int half = 0; half < 2; half++) {
                const int r = rbase + half * 8;
                float a0 = acc[nt][half * 2 + 0];
                float a1 = acc[nt][half * 2 + 1];
                __nv_bfloat16 *hiA, *loA;
                int col;
                if (cc < 64) {
                    col = cc;
                    a0 = (a0 + bq[col]) * QSCALE;
                    a1 = (a1 + bq[col + 1]) * QSCALE;
                    hiA = g_qhi; loA = g_qlo;
                } else if (cc < 128) {
                    col = cc - 64;
                    a0 += bk[col]; a1 += bk[col + 1];
                    hiA = g_khi; loA = g_klo;
                } else {
                    col = cc - 128;
                    a0 += bv[col]; a1 += bv[col + 1];
                    hiA = g_vhi; loA = g_vlo;
                }
                uint32_t hw, lw;
                split2(a0, a1, hw, lw);
                const size_t idx = (size_t)r * HEAD + col;
                *reinterpret_cast<uint32_t*>(hiA + idx) = hw;
                *reinterpret_cast<uint32_t*>(loA + idx) = lw;
            }
        }
    }
}

// ===========================================================================
// Kernel 2: split-K flash attention, BQ=128, warp-M=32 (B-frag reuse x2).
// 128 threads / 4 warps; Q-hi frags in regs, Q-lo persistent in smem.
// nsp = ceil(nk/24) -> 60 chunks/batch -> grid 240 = one wave @ 2 CTA/SM.
// ===========================================================================
#define BQ 128
#define BK 64
#define STRIDE 144

#define SM_QLO   0                   // persistent Q-lo: 128*144 = 18432
#define SM_STAGE 18432
#define STAGE_SZ 36864
#define OFF_KHI  0
#define OFF_KLO  9216
#define OFF_VHI  18432
#define OFF_VLO  27648
#define SM_TOTAL (SM_STAGE + 2 * STAGE_SZ)   // 92160

#define ATTN_GRID (BATCH * 60)               // 240

__global__ __launch_bounds__(128, 2) void attn_mma_kernel(float* __restrict__ out)
{
    extern __shared__ char smem[];
    const uint32_t sbase = smem_u32(smem);

    const int b = blockIdx.x & 3;
    int i = blockIdx.x >> 2;         // 0..59
    int qt = 0, s = i;
#pragma unroll 1
    for (qt = 0; qt < 32; qt++) {
        const int c = (2 * qt + 25) / 24;    // nsp(qt)
        if (s < c) break;
        s -= c;
    }
    const int nk  = 2 * qt + 2;
    const int nsp = (2 * qt + 25) / 24;
    const int chn = (nk + nsp - 1) / nsp;
    const int k0  = s * chn;
    const int k1  = (k0 + chn < nk) ? (k0 + chn) : nk;
    const int cnt = k1 - k0;
    const int q0  = qt * BQ;

    const int tid  = threadIdx.x;
    const int warp = tid >> 5;
    const int lane = tid & 31;
    const int g    = lane >> 2;
    const int qr   = lane & 3;
    const int R    = warp * 32;      // warp covers rows R..R+31

    auto prefetch_k = [&](int kt, int stage) {
        const uint32_t sb = sbase + SM_STAGE + stage * STAGE_SZ;
        const size_t gro = (size_t)(b * SEQ) + (size_t)kt * BK;
#pragma unroll
        for (int t = 0; t < 8; t++) {
            const int ii  = tid + t * 128;
            const int arr = ii >> 9;
            const int rem = ii & 511;
            const int r = rem >> 3, c = rem & 7;
            const __nv_bfloat16* base = arr ? g_klo : g_khi;
            const uint32_t off = arr ? OFF_KLO : OFF_KHI;
            cp_async16(sb + off + r * STRIDE + c * 16,
                       base + (gro + r) * HEAD + c * 8);
        }
    };
    auto prefetch_v = [&](int kt, int stage) {
        const uint32_t sb = sbase + SM_STAGE + stage * STAGE_SZ;
        const size_t gro = (size_t)(b * SEQ) + (size_t)kt * BK;
#pragma unroll
        for (int t = 0; t < 8; t++) {
            const int ii  = tid + t * 128;
            const int arr = ii >> 9;
            const int rem = ii & 511;
            const int r = rem >> 3, c = rem & 7;
            const __nv_bfloat16* base = arr ? g_vlo : g_vhi;
            const uint32_t off = arr ? OFF_VLO : OFF_VHI;
            cp_async16(sb + off + r * STRIDE + c * 16,
                       base + (gro + r) * HEAD + c * 8);
        }
    };

    // ---- prologue: Q-hi staged transiently in stage0, Q-lo persistent ----
    for (int ii = tid; ii < 2048; ii += 128) {
        const int arr = ii >> 10;              // 0 hi, 1 lo
        const int rem = ii & 1023;
        const int r = rem >> 3, c = rem & 7;   // 128 rows x 8 chunks
        const __nv_bfloat16* src = (arr ? g_qlo : g_qhi)
            + ((size_t)(b * SEQ) + q0 + r) * HEAD + c * 8;
        const int4 val = *reinterpret_cast<const int4*>(src);
        *reinterpret_cast<int4*>(smem + (arr ? SM_QLO : SM_STAGE)
                                 + r * STRIDE + c * 16) = val;
    }
    __syncthreads();

    uint32_t qahi[2][4][4];
    {
        const uint32_t aQhi = sbase + SM_STAGE
            + (uint32_t)(R + (lane & 15)) * STRIDE + ((lane >> 4) * 8) * 2;
#pragma unroll
        for (int mt = 0; mt < 2; mt++)
#pragma unroll
            for (int kc = 0; kc < 4; kc++)
                ldsm4(aQhi + mt * (16 * STRIDE) + kc * 32, qahi[mt][kc]);
    }
    __syncthreads();   // Q-hi frags held before staging area reused by K/V

    prefetch_k(k0, 0); CP_COMMIT();
    prefetch_v(k0, 0); CP_COMMIT();

    const uint32_t aQlo = sbase + SM_QLO
        + (uint32_t)(R + (lane & 15)) * STRIDE + ((lane >> 4) * 8) * 2;
    const uint32_t oK = (uint32_t)(((lane >> 4) & 1) * 8 + (lane & 7)) * STRIDE
        + (((lane >> 3) & 1) * 8) * 2;
    const uint32_t oV = (uint32_t)(((lane >> 3) & 1) * 8 + (lane & 7)) * STRIDE
        + (((lane >> 4) & 1) * 8) * 2;

    float oacc[2][8][4];
#pragma unroll
    for (int mt = 0; mt < 2; mt++)
#pragma unroll
        for (int nt = 0; nt < 8; nt++)
#pragma unroll
            for (int e = 0; e < 4; e++) oacc[mt][nt][e] = 0.0f;
    float mr[2][2], lr[2][2];
#pragma unroll
    for (int mt = 0; mt < 2; mt++) {
        mr[mt][0] = -1e30f; mr[mt][1] = -1e30f;
        lr[mt][0] = 0.0f;   lr[mt][1] = 0.0f;
    }

    uint32_t aphi[2][4][4], aplo[2][4][4];   // loop-carried P (tile j-1)

    for (int j = 0; j < cnt; j++) {
        const int kt = k0 + j;
        asm volatile("cp.async.wait_group 1;" ::: "memory");
        __syncthreads();
        if (j + 1 < cnt) { prefetch_k(kt + 1, (j + 1) & 1); CP_COMMIT(); }

        const uint32_t bK = sbase + SM_STAGE + (j & 1) * STAGE_SZ + OFF_KHI + oK;

        // ---- S(j): 3-pass emulation, both m-tiles share B frags ----
        float sacc[2][8][4];
#pragma unroll
        for (int mt = 0; mt < 2; mt++)
#pragma unroll
            for (int nt = 0; nt < 8; nt++)
#pragma unroll
                for (int e = 0; e < 4; e++) sacc[mt][nt][e] = 0.0f;

#pragma unroll
        for (int kc = 0; kc < 4; kc++) {
            uint32_t al0[4], al1[4];
            ldsm4(aQlo + kc * 32, al0);
            ldsm4(aQlo + 16 * STRIDE + kc * 32, al1);
#pragma unroll
            for (int np = 0; np < 4; np++) {
                uint32_t bh[4], bl[4];
                ldsm4(bK + np * (16 * STRIDE) + kc * 32, bh);
                ldsm4(bK + 9216 + np * (16 * STRIDE) + kc * 32, bl);
                mma16816(sacc[0][2 * np],     qahi[0][kc], bh[0], bh[1]);
                mma16816(sacc[0][2 * np],     qahi[0][kc], bl[0], bl[1]);
                mma16816(sacc[0][2 * np],     al0, bh[0], bh[1]);
                mma16816(sacc[0][2 * np + 1], qahi[0][kc], bh[2], bh[3]);
                mma16816(sacc[0][2 * np + 1], qahi[0][kc], bl[2], bl[3]);
                mma16816(sacc[0][2 * np + 1], al0, bh[2], bh[3]);
                mma16816(sacc[1][2 * np],     qahi[1][kc], bh[0], bh[1]);
                mma16816(sacc[1][2 * np],     qahi[1][kc], bl[0], bl[1]);
                mma16816(sacc[1][2 * np],     al1, bh[0], bh[1]);
                mma16816(sacc[1][2 * np + 1], qahi[1][kc], bh[2], bh[3]);
                mma16816(sacc[1][2 * np + 1], qahi[1][kc], bl[2], bl[3]);
                mma16816(sacc[1][2 * np + 1], al1, bh[2], bh[3]);
            }
        }

        // ---- PV(j-1): drains while softmax(j) runs; B frags shared ----
        if (j > 0) {
            const uint32_t bV = sbase + SM_STAGE + ((j & 1) ^ 1) * STAGE_SZ + OFF_VHI + oV;
#pragma unroll
            for (int kc2 = 0; kc2 < 4; kc2++) {
#pragma unroll
                for (int np = 0; np < 4; np++) {
                    uint32_t bvh[4], bvl[4];
                    ldsm4t(bV + kc2 * (16 * STRIDE) + np * 32, bvh);
                    ldsm4t(bV + 9216 + kc2 * (16 * STRIDE) + np * 32, bvl);
#pragma unroll
                    for (int mt = 0; mt < 2; mt++) {
                        mma16816(oacc[mt][2 * np],     aphi[mt][kc2], bvh[0], bvh[1]);
                        mma16816(oacc[mt][2 * np],     aphi[mt][kc2], bvl[0], bvl[1]);
                        mma16816(oacc[mt][2 * np],     aplo[mt][kc2], bvh[0], bvh[1]);
                        mma16816(oacc[mt][2 * np + 1], aphi[mt][kc2], bvh[2], bvh[3]);
                        mma16816(oacc[mt][2 * np + 1], aphi[mt][kc2], bvl[2], bvl[3]);
                        mma16816(oacc[mt][2 * np + 1], aplo[mt][kc2], bvh[2], bvh[3]);
                    }
                }
            }
        }
        __syncthreads();
        if (j + 1 < cnt) { prefetch_v(kt + 1, (j + 1) & 1); CP_COMMIT(); }

        // ---- causal mask (last two k-tiles only) ----
        if (kt * 64 >= q0) {
            const int mb = q0 - kt * 64;     // 0 or -64
#pragma unroll
            for (int mt = 0; mt < 2; mt++) {
                const int r0 = R + mt * 16 + g, r1 = r0 + 8;
#pragma unroll
                for (int nt = 0; nt < 8; nt++) {
                    const int lc = nt * 8 + qr * 2;
                    if (lc > mb + r0)     sacc[mt][nt][0] = -1e30f;
                    if (lc + 1 > mb + r0) sacc[mt][nt][1] = -1e30f;
                    if (lc > mb + r1)     sacc[mt][nt][2] = -1e30f;
                    if (lc + 1 > mb + r1) sacc[mt][nt][3] = -1e30f;
                }
            }
        }

        // ---- softmax(j), base-2, 4 row-states per thread ----
#pragma unroll
        for (int mt = 0; mt < 2; mt++) {
            float m0 = -1e30f, m1 = -1e30f;
#pragma unroll
            for (int nt = 0; nt < 8; nt++) {
                m0 = fmaxf(m0, fmaxf(sacc[mt][nt][0], sacc[mt][nt][1]));
                m1 = fmaxf(m1, fmaxf(sacc[mt][nt][2], sacc[mt][nt][3]));
            }
            m0 = fmaxf(m0, __shfl_xor_sync(0xffffffffu, m0, 1));
            m0 = fmaxf(m0, __shfl_xor_sync(0xffffffffu, m0, 2));
            m1 = fmaxf(m1, __shfl_xor_sync(0xffffffffu, m1, 1));
            m1 = fmaxf(m1, __shfl_xor_sync(0xffffffffu, m1, 2));

            const float mn0 = fmaxf(mr[mt][0], m0);
            const float mn1 = fmaxf(mr[mt][1], m1);
            const float corr0 = exp2f(mr[mt][0] - mn0);
            const float corr1 = exp2f(mr[mt][1] - mn1);
            mr[mt][0] = mn0; mr[mt][1] = mn1;

            float ps0 = 0.0f, ps1 = 0.0f;
#pragma unroll
            for (int kc2 = 0; kc2 < 4; kc2++) {
                const int ntE = 2 * kc2, ntO = 2 * kc2 + 1;
                float pE0 = exp2f(sacc[mt][ntE][0] - mn0);
                float pE1 = exp2f(sacc[mt][ntE][1] - mn0);
                float pE2 = exp2f(sacc[mt][ntE][2] - mn1);
                float pE3 = exp2f(sacc[mt][ntE][3] - mn1);
                float pO0 = exp2f(sacc[mt][ntO][0] - mn0);
                float pO1 = exp2f(sacc[mt][ntO][1] - mn0);
                float pO2 = exp2f(sacc[mt][ntO][2] - mn1);
                float pO3 = exp2f(sacc[mt][ntO][3] - mn1);
                ps0 += pE0 + pE1 + pO0 + pO1;
                ps1 += pE2 + pE3 + pO2 + pO3;
                split2(pE0, pE1, aphi[mt][kc2][0], aplo[mt][kc2][0]);
                split2(pE2, pE3, aphi[mt][kc2][1], aplo[mt][kc2][1]);
                split2(pO0, pO1, aphi[mt][kc2][2], aplo[mt][kc2][2]);
                split2(pO2, pO3, aphi[mt][kc2][3], aplo[mt][kc2][3]);
            }
            ps0 += __shfl_xor_sync(0xffffffffu, ps0, 1);
            ps0 += __shfl_xor_sync(0xffffffffu, ps0, 2);
            ps1 += __shfl_xor_sync(0xffffffffu, ps1, 1);
            ps1 += __shfl_xor_sync(0xffffffffu, ps1, 2);
            lr[mt][0] = lr[mt][0] * corr0 + ps0;
            lr[mt][1] = lr[mt][1] * corr1 + ps1;

#pragma unroll
            for (int nt = 0; nt < 8; nt++) {
                oacc[mt][nt][0] *= corr0; oacc[mt][nt][1] *= corr0;
                oacc[mt][nt][2] *= corr1; oacc[mt][nt][3] *= corr1;
            }
        }
    }

    // ---- final PV(cnt-1) ----
    asm volatile("cp.async.wait_group 0;" ::: "memory");
    {
        const uint32_t bV = sbase + SM_STAGE + ((cnt - 1) & 1) * STAGE_SZ + OFF_VHI + oV;
#pragma unroll
        for (int kc2 = 0; kc2 < 4; kc2++) {
#pragma unroll
            for (int np = 0; np < 4; np++) {
                uint32_t bvh[4], bvl[4];
                ldsm4t(bV + kc2 * (16 * STRIDE) + np * 32, bvh);
                ldsm4t(bV + 9216 + kc2 * (16 * STRIDE) + np * 32, bvl);
#pragma unroll
                for (int mt = 0; mt < 2; mt++) {
                    mma16816(oacc[mt][2 * np],     aphi[mt][kc2], bvh[0], bvh[1]);
                    mma16816(oacc[mt][2 * np],     aphi[mt][kc2], bvl[0], bvl[1]);
                    mma16816(oacc[mt][2 * np],     aplo[mt][kc2], bvh[0], bvh[1]);
                    mma16816(oacc[mt][2 * np + 1], aphi[mt][kc2], bvh[2], bvh[3]);
                    mma16816(oacc[mt][2 * np + 1], aphi[mt][kc2], bvl[2], bvl[3]);
                    mma16816(oacc[mt][2 * np + 1], aplo[mt][kc2], bvh[2], bvh[3]);
                }
            }
        }
    }

    // ---- epilogue ----
    if (nsp == 1) {
#pragma unroll
        for (int mt = 0; mt < 2; mt++) {
            const float inv0 = 1.0f / lr[mt][0];
            const float inv1 = 1.0f / lr[mt][1];
            const size_t row0 = (size_t)(b * SEQ) + q0 + R + mt * 16 + g;
            const size_t row1 = row0 + 8;
#pragma unroll
            for (int nt = 0; nt < 8; nt++) {
                const int col = nt * 8 + qr * 2;
                float2 o0; o0.x = oacc[mt][nt][0] * inv0; o0.y = oacc[mt][nt][1] * inv0;
                float2 o1; o1.x = oacc[mt][nt][2] * inv1; o1.y = oacc[mt][nt][3] * inv1;
                *reinterpret_cast<float2*>(out + row0 * HEAD + col) = o0;
                *reinterpret_cast<float2*>(out + row1 * HEAD + col) = o1;
            }
        }
    } else {
        const int pidx = ((b * 32 + qt) * 4 + s);
        float* op = g_opart + (size_t)pidx * 8192;
#pragma unroll
        for (int mt = 0; mt < 2; mt++) {
            const int r0 = R + mt * 16 + g;
#pragma unroll
            for (int nt = 0; nt < 8; nt++) {
                const int col = nt * 8 + qr * 2;
                float2 o0; o0.x = oacc[mt][nt][0]; o0.y = oacc[mt][nt][1];
                float2 o1; o1.x = oacc[mt][nt][2]; o1.y = oacc[mt][nt][3];
                *reinterpret_cast<float2*>(op + r0 * 64 + col) = o0;
                *reinterpret_cast<float2*>(op + (r0 + 8) * 64 + col) = o1;
            }
            if (qr == 0) {
                g_mpart[pidx * 128 + r0]     = mr[mt][0];
                g_mpart[pidx * 128 + r0 + 8] = mr[mt][1];
                g_lpart[pidx * 128 + r0]     = lr[mt][0];
                g_lpart[pidx * 128 + r0 + 8] = lr[mt][1];
            }
        }
    }
}

// ===========================================================================
// Kernel 3: split-K merge (base-2 weights), BQ=128 layout.
// ===========================================================================
__global__ __launch_bounds__(256) void merge_kernel(float* __restrict__ out)
{
    const int b  = blockIdx.x & 3;
    const int qt = blockIdx.x >> 2;          // 0..31
    const int nsp = (2 * qt + 25) / 24;
    if (nsp == 1) return;

    const int tid = threadIdx.x;
    const int row = tid >> 1;                // 0..127
    const int ch  = (tid & 1) * 32;

    const int pbase = (b * 32 + qt) * 4;
    float m[4], lv[4];
    float M = -1e30f;
    for (int s = 0; s < nsp; s++) {
        m[s]  = g_mpart[(pbase + s) * 128 + row];
        lv[s] = g_lpart[(pbase + s) * 128 + row];
        M = fmaxf(M, m[s]);
    }
    float w[4];
    float L = 0.0f;
    for (int s = 0; s < nsp; s++) {
        w[s] = exp2f(m[s] - M);
        L += lv[s] * w[s];
    }
    const float inv = 1.0f / L;

    float* o = out + ((size_t)(b * SEQ) + qt * 128 + row) * HEAD + ch;
#pragma unroll
    for (int c4 = 0; c4 < 8; c4++) {
        float4 acc = make_float4(0.f, 0.f, 0.f, 0.f);
        for (int s = 0; s < nsp; s++) {
            const float4 v = *reinterpret_cast<const float4*>(
                g_opart + (size_t)(pbase + s) * 8192 + row * 64 + ch + c4 * 4);
            acc.x += w[s] * v.x; acc.y += w[s] * v.y;
            acc.z += w[s] * v.z; acc.w += w[s] * v.w;
        }
        acc.x *= inv; acc.y *= inv; acc.z *= inv; acc.w *= inv;
        *reinterpret_cast<float4*>(o + c4 * 4) = acc;
    }
}

// ===========================================================================
extern "C" void kernel_launch(void* const* d_in, const int* in_sizes, int n_in,
                              void* d_out, int out_size)
{
    const float* x  = (const float*)d_in[0];
    const float* Wq = (const float*)d_in[1];
    const float* bq = (const float*)d_in[2];
    const float* Wk = (const float*)d_in[3];
    const float* bk = (const float*)d_in[4];
    const float* Wv = (const float*)d_in[5];
    const float* bv = (const float*)d_in[6];
    float* out = (float*)d_out;

    wconv_kernel<<<192, 256>>>(Wq, Wk, Wv);

    {
        cudaFuncSetAttribute(qkv_mma_kernel,
                             cudaFuncAttributeMaxDynamicSharedMemorySize, QK_SMEM);
        qkv_mma_kernel<<<128, 512, QK_SMEM>>>(x, bq, bk, bv);
    }

    {
        cudaFuncSetAttribute(attn_mma_kernel,
                             cudaFuncAttributeMaxDynamicSharedMemorySize, SM_TOTAL);
        attn_mma_kernel<<<ATTN_GRID, 128, SM_TOTAL>>>(out);
    }

    merge_kernel<<<128, 256>>>(out);
}

// round 17
// speedup vs baseline: 1.1450x; 1.1450x over previous
#include <cuda_runtime.h>
#include <cuda_bf16.h>
#include <math.h>
#include <cstdint>

#define BATCH 4
#define SEQ   4096
#define EMB   1024
#define HEAD  64

// bf16 hi/lo split of projected q (pre-scaled by 0.125*log2e), k, v. 2 MB each.
__device__ __nv_bfloat16 g_qhi[BATCH * SEQ * HEAD];
__device__ __nv_bfloat16 g_qlo[BATCH * SEQ * HEAD];
__device__ __nv_bfloat16 g_khi[BATCH * SEQ * HEAD];
__device__ __nv_bfloat16 g_klo[BATCH * SEQ * HEAD];
__device__ __nv_bfloat16 g_vhi[BATCH * SEQ * HEAD];
__device__ __nv_bfloat16 g_vlo[BATCH * SEQ * HEAD];

// W^T hi/lo: [n=192][k=1024]
__device__ __nv_bfloat16 g_wthi[192 * 1024];
__device__ __nv_bfloat16 g_wtlo[192 * 1024];

// split-K partials
__device__ float g_opart[BATCH * 64 * 4 * 64 * 64];   // 16 MB
__device__ float g_mpart[BATCH * 64 * 4 * 64];
__device__ float g_lpart[BATCH * 64 * 4 * 64];

#define QSCALE 0.18033688011112042f   // 0.125 * log2(e)

// ===========================================================================
// helpers
// ===========================================================================
__device__ __forceinline__ uint32_t smem_u32(const void* p) {
    uint32_t a;
    asm("{ .reg .u64 t; cvta.to.shared.u64 t, %1; cvt.u32.u64 %0, t; }"
        : "=r"(a) : "l"(p));
    return a;
}

__device__ __forceinline__ void ldsm4(uint32_t addr, uint32_t* r) {
    asm volatile("ldmatrix.sync.aligned.m8n8.x4.shared.b16 {%0,%1,%2,%3}, [%4];"
        : "=r"(r[0]), "=r"(r[1]), "=r"(r[2]), "=r"(r[3]) : "r"(addr));
}
__device__ __forceinline__ void ldsm4t(uint32_t addr, uint32_t* r) {
    asm volatile("ldmatrix.sync.aligned.m8n8.x4.trans.shared.b16 {%0,%1,%2,%3}, [%4];"
        : "=r"(r[0]), "=r"(r[1]), "=r"(r[2]), "=r"(r[3]) : "r"(addr));
}

__device__ __forceinline__ void mma16816(float* c, const uint32_t* a,
                                         uint32_t b0, uint32_t b1) {
    asm volatile(
        "mma.sync.aligned.m16n8k16.row.col.f32.bf16.bf16.f32 "
        "{%0,%1,%2,%3}, {%4,%5,%6,%7}, {%8,%9}, {%0,%1,%2,%3};"
        : "+f"(c[0]), "+f"(c[1]), "+f"(c[2]), "+f"(c[3])
        : "r"(a[0]), "r"(a[1]), "r"(a[2]), "r"(a[3]), "r"(b0), "r"(b1));
}

__device__ __forceinline__ void cp_async16(uint32_t saddr, const void* gaddr) {
    asm volatile("cp.async.cg.shared.global [%0], [%1], 16;"
        :: "r"(saddr), "l"(gaddr) : "memory");
}
#define CP_COMMIT() asm volatile("cp.async.commit_group;" ::: "memory")

#define STS128(r0, r1, r2, r3, addr) \
    asm volatile("st.shared.v4.b32 [%0], {%1, %2, %3, %4};" \
        :: "r"(addr), "r"(r0), "r"(r1), "r"(r2), "r"(r3) : "memory")

// fast fp32 pair -> bf16 hi word + bf16 residual word (rn, exact residual)
__device__ __forceinline__ void split2(float x0, float x1,
                                       uint32_t& hw, uint32_t& lw) {
    asm("cvt.rn.bf16x2.f32 %0, %1, %2;" : "=r"(hw) : "f"(x1), "f"(x0));
    const float h0 = __uint_as_float(hw << 16);
    const float h1 = __uint_as_float(hw & 0xFFFF0000u);
    const float l0 = x0 - h0;
    const float l1 = x1 - h1;
    asm("cvt.rn.bf16x2.f32 %0, %1, %2;" : "=r"(lw) : "f"(l1), "f"(l0));
}

// ===========================================================================
// Kernel 0: W^T hi/lo precompute — simple version (6.4us measured)
// ===========================================================================
__global__ __launch_bounds__(256) void wconv_kernel(
    const float* __restrict__ Wq, const float* __restrict__ Wk,
    const float* __restrict__ Wv)
{
    const int n = blockIdx.x;
    const float* W;
    int nn;
    if (n < 64)       { W = Wq; nn = n; }
    else if (n < 128) { W = Wk; nn = n - 64; }
    else              { W = Wv; nn = n - 128; }
    for (int k = threadIdx.x; k < 1024; k += 256) {
        float v = W[(size_t)k * HEAD + nn];
        __nv_bfloat16 h = __float2bfloat16(v);
        float l = v - __bfloat162float(h);
        g_wthi[(size_t)n * 1024 + k] = h;
        g_wtlo[(size_t)n * 1024 + k] = __float2bfloat16(l);
    }
}

// ===========================================================================
// Kernel 1: QKV projection on mma.sync (3xBF16). 512 threads, 16 warps.
// ===========================================================================
#define QK_STG  92160
#define QX_HI   0
#define QX_LO   18432
#define QW_HI   36864
#define QW_LO   64512
#define QK_SMEM (2 * QK_STG)
#define NCH     (EMB / 64)

__global__ __launch_bounds__(512, 1) void qkv_mma_kernel(
    const float* __restrict__ x,
    const float* __restrict__ bq, const float* __restrict__ bk,
    const float* __restrict__ bv)
{
    extern __shared__ char smem[];
    const uint32_t sbase = smem_u32(smem);
    const int tid  = threadIdx.x;
    const int warp = tid >> 5;
    const int lane = tid & 31;
    const int g    = lane >> 2;
    const int qr   = lane & 3;
    const int warpM = warp >> 1;
    const int warpN = warp & 1;
    const int m0 = blockIdx.x * 128;

    const int xrow = tid >> 2;
    const int xq   = (tid & 3) * 16;

    float xr[16];

    auto ldX = [&](int c) {
        const float4* src = reinterpret_cast<const float4*>(
            x + (size_t)(m0 + xrow) * EMB + c * 64 + xq);
#pragma unroll
        for (int j = 0; j < 4; j++) {
            float4 v = src[j];
            xr[j * 4 + 0] = v.x; xr[j * 4 + 1] = v.y;
            xr[j * 4 + 2] = v.z; xr[j * 4 + 3] = v.w;
        }
    };

    auto stX = [&](int s) {
        const uint32_t dst = sbase + s * QK_STG
            + (uint32_t)xrow * 144 + xq * 2;
        uint32_t hw[8], lw[8];
#pragma unroll
        for (int p = 0; p < 8; p++)
            split2(xr[p * 2], xr[p * 2 + 1], hw[p], lw[p]);
        STS128(hw[0], hw[1], hw[2], hw[3], dst + QX_HI);
        STS128(hw[4], hw[5], hw[6], hw[7], dst + QX_HI + 16);
        STS128(lw[0], lw[1], lw[2], lw[3], dst + QX_LO);
        STS128(lw[4], lw[5], lw[6], lw[7], dst + QX_LO + 16);
    };

    auto cpW = [&](int c, int s) {
        const uint32_t base = sbase + s * QK_STG;
#pragma unroll
        for (int t = 0; t < 6; t++) {
            const int i   = tid + t * 512;
            const int arr = (i >= 1536) ? 1 : 0;
            const int i2  = arr ? (i - 1536) : i;
            const int row = i2 >> 3, ch = i2 & 7;
            const __nv_bfloat16* src = (arr ? g_wtlo : g_wthi)
                + (size_t)row * 1024 + c * 64 + ch * 8;
            cp_async16(base + (arr ? QW_LO : QW_HI) + row * 144 + ch * 16, src);
        }
        CP_COMMIT();
    };

    float acc[12][4];
#pragma unroll
    for (int nt = 0; nt < 12; nt++)
#pragma unroll
        for (int e = 0; e < 4; e++) acc[nt][e] = 0.0f;

    ldX(0);
    cpW(0, 0);

    for (int c = 0; c < NCH; c++) {
        const int s = c & 1;
        __syncthreads();
        stX(s);
        if (c + 1 < NCH) {
            cpW(c + 1, s ^ 1);
            asm volatile("cp.async.wait_group 1;" ::: "memory");
        } else {
            asm volatile("cp.async.wait_group 0;" ::: "memory");
        }
        __syncthreads();
        if (c + 1 < NCH) ldX(c + 1);

        const uint32_t xb = sbase + s * QK_STG + QX_HI
            + (uint32_t)(warpM * 16 + (lane & 15)) * 144 + (lane >> 4) * 16;
        const uint32_t wb = sbase + s * QK_STG + QW_HI
            + (uint32_t)(warpN * 96 + ((lane >> 4) & 1) * 8 + (lane & 7)) * 144
            + ((lane >> 3) & 1) * 16;

#pragma unroll
        for (int kc = 0; kc < 4; kc++) {
            uint32_t ah[4], al[4];
            ldsm4(xb + kc * 32, ah);
            ldsm4(xb + (QX_LO - QX_HI) + kc * 32, al);
#pragma unroll
            for (int nt = 0; nt < 6; nt++) {
                uint32_t bh[4], bl[4];
                ldsm4(wb + nt * (16 * 144) + kc * 32, bh);
                ldsm4(wb + (QW_LO - QW_HI) + nt * (16 * 144) + kc * 32, bl);
                mma16816(acc[2 * nt],     ah, bh[0], bh[1]);
                mma16816(acc[2 * nt],     ah, bl[0], bl[1]);
                mma16816(acc[2 * nt],     al, bh[0], bh[1]);
                mma16816(acc[2 * nt + 1], ah, bh[2], bh[3]);
                mma16816(acc[2 * nt + 1], ah, bl[2], bl[3]);
                mma16816(acc[2 * nt + 1], al, bh[2], bh[3]);
            }
        }
    }

    {
        const int rbase = m0 + warpM * 16 + g;
#pragma unroll
        for (int nt = 0; nt < 12; nt++) {
            const int cc = warpN * 96 + nt * 8 + qr * 2;
#pragma unroll
            for (int half = 0; half < 2; half++) {
                const int r = rbase + half * 8;
                float a0 = acc[nt][half * 2 + 0];
                float a1 = acc[nt][half * 2 + 1];
                __nv_bfloat16 *hiA, *loA;
                int col;
                if (cc < 64) {
                    col = cc;
                    a0 = (a0 + bq[col]) * QSCALE;
                    a1 = (a1 + bq[col + 1]) * QSCALE;
                    hiA = g_qhi; loA = g_qlo;
                } else if (cc < 128) {
                    col = cc - 64;
                    a0 += bk[col]; a1 += bk[col + 1];
                    hiA = g_khi; loA = g_klo;
                } else {
                    col = cc - 128;
                    a0 += bv[col]; a1 += bv[col + 1];
                    hiA = g_vhi; loA = g_vlo;
                }
                uint32_t hw, lw;
                split2(a0, a1, hw, lw);
                const size_t idx = (size_t)r * HEAD + col;
                *reinterpret_cast<uint32_t*>(hiA + idx) = hw;
                *reinterpret_cast<uint32_t*>(loA + idx) = lw;
            }
        }
    }
}

// ===========================================================================
// Kernel 2: split-K flash attention. BQ=64, 73728B smem -> 3 CTAs/SM.
// nsp = (nk+26)/27 -> 111 chunks/batch -> grid 444 = exactly one wave.
// (R15 body, measured 182.7us total.)
// ===========================================================================
#define BQ 64
#define BK 64
#define STRIDE 144

#define STAGE_SZ 36864
#define OFF_KHI  0
#define OFF_KLO  9216
#define OFF_VHI  18432
#define OFF_VLO  27648
#define SM_TOTAL (2 * STAGE_SZ)              // 73728

#define ATTN_GRID (BATCH * 111)              // 444 = 3 * 148

__global__ __launch_bounds__(128, 3) void attn_mma_kernel(float* __restrict__ out)
{
    extern __shared__ char smem[];
    const uint32_t sbase = smem_u32(smem);

    const int b = blockIdx.x & 3;
    int i = blockIdx.x >> 2;
    int qt = 0, s = i;
#pragma unroll 1
    for (qt = 0; qt < 64; qt++) {
        const int c = (qt + 27) / 27;        // nsp(qt)
        if (s < c) break;
        s -= c;
    }
    const int nk  = qt + 1;
    const int nsp = (qt + 27) / 27;
    const int chn = (nk + nsp - 1) / nsp;
    const int k0  = s * chn;
    const int k1  = (k0 + chn < nk) ? (k0 + chn) : nk;
    const int cnt = k1 - k0;
    const int q0  = qt * BQ;

    const int tid  = threadIdx.x;
    const int warp = tid >> 5;
    const int lane = tid & 31;
    const int g    = lane >> 2;
    const int qr   = lane & 3;
    const int R    = warp * 16;

    auto prefetch_k = [&](int kt, int stage) {
        const uint32_t sb = sbase + stage * STAGE_SZ;
        const size_t gro = (size_t)(b * SEQ) + (size_t)kt * BK;
#pragma unroll
        for (int t = 0; t < 8; t++) {
            const int ii  = tid + t * 128;
            const int arr = ii >> 9;
            const int rem = ii & 511;
            const int r = rem >> 3, c = rem & 7;
            const __nv_bfloat16* base = arr ? g_klo : g_khi;
            const uint32_t off = arr ? OFF_KLO : OFF_KHI;
            cp_async16(sb + off + r * STRIDE + c * 16,
                       base + (gro + r) * HEAD + c * 8);
        }
    };
    auto prefetch_v = [&](int kt, int stage) {
        const uint32_t sb = sbase + stage * STAGE_SZ;
        const size_t gro = (size_t)(b * SEQ) + (size_t)kt * BK;
#pragma unroll
        for (int t = 0; t < 8; t++) {
            const int ii  = tid + t * 128;
            const int arr = ii >> 9;
            const int rem = ii & 511;
            const int r = rem >> 3, c = rem & 7;
            const __nv_bfloat16* base = arr ? g_vlo : g_vhi;
            const uint32_t off = arr ? OFF_VLO : OFF_VHI;
            cp_async16(sb + off + r * STRIDE + c * 16,
                       base + (gro + r) * HEAD + c * 8);
        }
    };

    // ---- prologue: stage Q transiently in stage-0 space, grab fragments ----
    for (int ii = tid; ii < 1024; ii += 128) {
        const int arr = ii >> 9;
        const int rem = ii & 511;
        const int r = rem >> 3, c = rem & 7;
        const __nv_bfloat16* src = (arr == 0 ? g_qhi : g_qlo)
            + ((size_t)(b * SEQ) + q0 + r) * HEAD + c * 8;
        const int4 val = *reinterpret_cast<const int4*>(src);
        *reinterpret_cast<int4*>(smem + arr * 9216 + r * STRIDE + c * 16) = val;
    }
    __syncthreads();

    const uint32_t aQ = sbase
        + (uint32_t)(R + (lane & 15)) * STRIDE + ((lane >> 4) * 8) * 2;
    uint32_t qahi[4][4], qalo[4][4];
#pragma unroll
    for (int kc = 0; kc < 4; kc++) {
        ldsm4(aQ + kc * 32, qahi[kc]);
        ldsm4(aQ + 9216 + kc * 32, qalo[kc]);
    }
    __syncthreads();   // all warps hold Q frags before staging area is reused

    prefetch_k(k0, 0); CP_COMMIT();
    prefetch_v(k0, 0); CP_COMMIT();

    const uint32_t oK = (uint32_t)(((lane >> 4) & 1) * 8 + (lane & 7)) * STRIDE
        + (((lane >> 3) & 1) * 8) * 2;
    const uint32_t oV = (uint32_t)(((lane >> 3) & 1) * 8 + (lane & 7)) * STRIDE
        + (((lane >> 4) & 1) * 8) * 2;

    float oacc[8][4];
#pragma unroll
    for (int nt = 0; nt < 8; nt++)
#pragma unroll
        for (int e = 0; e < 4; e++) oacc[nt][e] = 0.0f;
    float mr0 = -1e30f, mr1 = -1e30f, l0 = 0.0f, l1 = 0.0f;

    uint32_t aphi[4][4], aplo[4][4];   // loop-carried P fragments (tile j-1)

    for (int j = 0; j < cnt; j++) {
        const int kt = k0 + j;
        asm volatile("cp.async.wait_group 1;" ::: "memory");
        __syncthreads();
        if (j + 1 < cnt) { prefetch_k(kt + 1, (j + 1) & 1); CP_COMMIT(); }

        const uint32_t bK = sbase + (j & 1) * STAGE_SZ + OFF_KHI + oK;

        // ---- S(j): 3-pass emulation ----
        float sacc[8][4];
#pragma unroll
        for (int nt = 0; nt < 8; nt++)
#pragma unroll
            for (int e = 0; e < 4; e++) sacc[nt][e] = 0.0f;

#pragma unroll
        for (int kc = 0; kc < 4; kc++) {
#pragma unroll
            for (int np = 0; np < 4; np++) {
                uint32_t bh[4], bl[4];
                ldsm4(bK + np * (16 * STRIDE) + kc * 32, bh);
                ldsm4(bK + 9216 + np * (16 * STRIDE) + kc * 32, bl);
                mma16816(sacc[2 * np],     qahi[kc], bh[0], bh[1]);
                mma16816(sacc[2 * np],     qahi[kc], bl[0], bl[1]);
                mma16816(sacc[2 * np],     qalo[kc], bh[0], bh[1]);
                mma16816(sacc[2 * np + 1], qahi[kc], bh[2], bh[3]);
                mma16816(sacc[2 * np + 1], qahi[kc], bl[2], bl[3]);
                mma16816(sacc[2 * np + 1], qalo[kc], bh[2], bh[3]);
            }
        }

        // ---- PV(j-1): latency hidden behind softmax(j) ----
        if (j > 0) {
            const uint32_t bV = sbase + ((j & 1) ^ 1) * STAGE_SZ + OFF_VHI + oV;
#pragma unroll
            for (int kc2 = 0; kc2 < 4; kc2++) {
#pragma unroll
                for (int np = 0; np < 4; np++) {
                    uint32_t bvh[4], bvl[4];
                    ldsm4t(bV + kc2 * (16 * STRIDE) + np * 32, bvh);
                    ldsm4t(bV + 9216 + kc2 * (16 * STRIDE) + np * 32, bvl);
                    mma16816(oacc[2 * np],     aphi[kc2], bvh[0], bvh[1]);
                    mma16816(oacc[2 * np],     aphi[kc2], bvl[0], bvl[1]);
                    mma16816(oacc[2 * np],     aplo[kc2], bvh[0], bvh[1]);
                    mma16816(oacc[2 * np + 1], aphi[kc2], bvh[2], bvh[3]);
                    mma16816(oacc[2 * np + 1], aphi[kc2], bvl[2], bvl[3]);
                    mma16816(oacc[2 * np + 1], aplo[kc2], bvh[2], bvh[3]);
                }
            }
        }
        __syncthreads();
        if (j + 1 < cnt) { prefetch_v(kt + 1, (j + 1) & 1); CP_COMMIT(); }

        // ---- softmax(j) (base-2) ----
        if (kt == qt) {
            const int lr0 = R + g, lr1 = R + g + 8;
#pragma unroll
            for (int nt = 0; nt < 8; nt++) {
                const int lc = nt * 8 + qr * 2;
                if (lc > lr0)     sacc[nt][0] = -1e30f;
                if (lc + 1 > lr0) sacc[nt][1] = -1e30f;
                if (lc > lr1)     sacc[nt][2] = -1e30f;
                if (lc + 1 > lr1) sacc[nt][3] = -1e30f;
            }
        }

        float m0 = -1e30f, m1 = -1e30f;
#pragma unroll
        for (int nt = 0; nt < 8; nt++) {
            m0 = fmaxf(m0, fmaxf(sacc[nt][0], sacc[nt][1]));
            m1 = fmaxf(m1, fmaxf(sacc[nt][2], sacc[nt][3]));
        }
        m0 = fmaxf(m0, __shfl_xor_sync(0xffffffffu, m0, 1));
        m0 = fmaxf(m0, __shfl_xor_sync(0xffffffffu, m0, 2));
        m1 = fmaxf(m1, __shfl_xor_sync(0xffffffffu, m1, 1));
        m1 = fmaxf(m1, __shfl_xor_sync(0xffffffffu, m1, 2));

        const float mn0 = fmaxf(mr0, m0);
        const float mn1 = fmaxf(mr1, m1);
        const float corr0 = exp2f(mr0 - mn0);
        const float corr1 = exp2f(mr1 - mn1);
        mr0 = mn0; mr1 = mn1;

        float ps0 = 0.0f, ps1 = 0.0f;
#pragma unroll
        for (int kc2 = 0; kc2 < 4; kc2++) {
            const int ntE = 2 * kc2, ntO = 2 * kc2 + 1;
            float pE0 = exp2f(sacc[ntE][0] - mn0);
            float pE1 = exp2f(sacc[ntE][1] - mn0);
            float pE2 = exp2f(sacc[ntE][2] - mn1);
            float pE3 = exp2f(sacc[ntE][3] - mn1);
            float pO0 = exp2f(sacc[ntO][0] - mn0);
            float pO1 = exp2f(sacc[ntO][1] - mn0);
            float pO2 = exp2f(sacc[ntO][2] - mn1);
            float pO3 = exp2f(sacc[ntO][3] - mn1);
            ps0 += pE0 + pE1 + pO0 + pO1;
            ps1 += pE2 + pE3 + pO2 + pO3;
            split2(pE0, pE1, aphi[kc2][0], aplo[kc2][0]);
            split2(pE2, pE3, aphi[kc2][1], aplo[kc2][1]);
            split2(pO0, pO1, aphi[kc2][2], aplo[kc2][2]);
            split2(pO2, pO3, aphi[kc2][3], aplo[kc2][3]);
        }
        ps0 += __shfl_xor_sync(0xffffffffu, ps0, 1);
        ps0 += __shfl_xor_sync(0xffffffffu, ps0, 2);
        ps1 += __shfl_xor_sync(0xffffffffu, ps1, 1);
        ps1 += __shfl_xor_sync(0xffffffffu, ps1, 2);
        l0 = l0 * corr0 + ps0;
        l1 = l1 * corr1 + ps1;

#pragma unroll
        for (int nt = 0; nt < 8; nt++) {
            oacc[nt][0] *= corr0; oacc[nt][1] *= corr0;
            oacc[nt][2] *= corr1; oacc[nt][3] *= corr1;
        }
    }

    // ---- final PV(cnt-1) ----
    asm volatile("cp.async.wait_group 0;" ::: "memory");
    {
        const uint32_t bV = sbase + ((cnt - 1) & 1) * STAGE_SZ + OFF_VHI + oV;
#pragma unroll
        for (int kc2 = 0; kc2 < 4; kc2++) {
#pragma unroll
            for (int np = 0; np < 4; np++) {
                uint32_t bvh[4], bvl[4];
                ldsm4t(bV + kc2 * (16 * STRIDE) + np * 32, bvh);
                ldsm4t(bV + 9216 + kc2 * (16 * STRIDE) + np * 32, bvl);
                mma16816(oacc[2 * np],     aphi[kc2], bvh[0], bvh[1]);
                mma16816(oacc[2 * np],     aphi[kc2], bvl[0], bvl[1]);
                mma16816(oacc[2 * np],     aplo[kc2], bvh[0], bvh[1]);
                mma16816(oacc[2 * np + 1], aphi[kc2], bvh[2], bvh[3]);
                mma16816(oacc[2 * np + 1], aphi[kc2], bvl[2], bvl[3]);
                mma16816(oacc[2 * np + 1], aplo[kc2], bvh[2], bvh[3]);
            }
        }
    }

    // ---- epilogue ----
    if (nsp == 1) {
        const float inv0 = 1.0f / l0;
        const float inv1 = 1.0f / l1;
        const size_t row0 = (size_t)(b * SEQ) + q0 + R + g;
        const size_t row1 = row0 + 8;
#pragma unroll
        for (int nt = 0; nt < 8; nt++) {
            const int col = nt * 8 + qr * 2;
            float2 o0; o0.x = oacc[nt][0] * inv0; o0.y = oacc[nt][1] * inv0;
            float2 o1; o1.x = oacc[nt][2] * inv1; o1.y = oacc[nt][3] * inv1;
            *reinterpret_cast<float2*>(out + row0 * HEAD + col) = o0;
            *reinterpret_cast<float2*>(out + row1 * HEAD + col) = o1;
        }
    } else {
        const int pidx = ((b * 64 + qt) * 4 + s);
        float* op = g_opart + (size_t)pidx * 4096;
#pragma unroll
        for (int nt = 0; nt < 8; nt++) {
            const int col = nt * 8 + qr * 2;
            float2 o0; o0.x = oacc[nt][0]; o0.y = oacc[nt][1];
            float2 o1; o1.x = oacc[nt][2]; o1.y = oacc[nt][3];
            *reinterpret_cast<float2*>(op + (R + g) * 64 + col) = o0;
            *reinterpret_cast<float2*>(op + (R + g + 8) * 64 + col) = o1;
        }
        if (qr == 0) {
            g_mpart[pidx * 64 + R + g]     = mr0;
            g_mpart[pidx * 64 + R + g + 8] = mr1;
            g_lpart[pidx * 64 + R + g]     = l0;
            g_lpart[pidx * 64 + R + g + 8] = l1;
        }
    }
}

// ===========================================================================
// Kernel 3: split-K merge (base-2 weights). Only qt >= 27 need merging:
// grid 148 = 4 batches x 37 q-tiles (qt = 27 + blockIdx>>2).
// ===========================================================================
__global__ __launch_bounds__(256) void merge_kernel(float* __restrict__ out)
{
    const int b  = blockIdx.x & 3;
    const int qt = 27 + (blockIdx.x >> 2);
    const int nsp = (qt + 27) / 27;

    const int tid = threadIdx.x;
    const int row = tid >> 2;
    const int cg  = tid & 3;

    const int pbase = (b * 64 + qt) * 4;
    float m[4], lv[4];
    float M = -1e30f;
    for (int s = 0; s < nsp; s++) {
        m[s]  = g_mpart[(pbase + s) * 64 + row];
        lv[s] = g_lpart[(pbase + s) * 64 + row];
        M = fmaxf(M, m[s]);
    }
    float w[4];
    float L = 0.0f;
    for (int s = 0; s < nsp; s++) {
        w[s] = exp2f(m[s] - M);
        L += lv[s] * w[s];
    }
    const float inv = 1.0f / L;

    float* o = out + ((size_t)(b * SEQ) + qt * 64 + row) * HEAD + cg * 16;
#pragma unroll
    for (int c4 = 0; c4 < 4; c4++) {
        float4 acc = make_float4(0.f, 0.f, 0.f, 0.f);
        for (int s = 0; s < nsp; s++) {
            const float4 v = *reinterpret_cast<const float4*>(
                g_opart + (size_t)(pbase + s) * 4096 + row * 64 + cg * 16 + c4 * 4);
            acc.x += w[s] * v.x; acc.y += w[s] * v.y;
            acc.z += w[s] * v.z; acc.w += w[s] * v.w;
        }
        acc.x *= inv; acc.y *= inv; acc.z *= inv; acc.w *= inv;
        *reinterpret_cast<float4*>(o + c4 * 4) = acc;
    }
}

// ===========================================================================
extern "C" void kernel_launch(void* const* d_in, const int* in_sizes, int n_in,
                              void* d_out, int out_size)
{
    const float* x  = (const float*)d_in[0];
    const float* Wq = (const float*)d_in[1];
    const float* bq = (const float*)d_in[2];
    const float* Wk = (const float*)d_in[3];
    const float* bk = (const float*)d_in[4];
    const float* Wv = (const float*)d_in[5];
    const float* bv = (const float*)d_in[6];
    float* out = (float*)d_out;

    wconv_kernel<<<192, 256>>>(Wq, Wk, Wv);

    {
        cudaFuncSetAttribute(qkv_mma_kernel,
                             cudaFuncAttributeMaxDynamicSharedMemorySize, QK_SMEM);
        qkv_mma_kernel<<<128, 512, QK_SMEM>>>(x, bq, bk, bv);
    }

    {
        cudaFuncSetAttribute(attn_mma_kernel,
                             cudaFuncAttributeMaxDynamicSharedMemorySize, SM_TOTAL);
        attn_mma_kernel<<<ATTN_GRID, 128, SM_TOTAL>>>(out);
    }

    merge_kernel<<<148, 256>>>(out);
}